// round 6
// baseline (speedup 1.0000x reference)
#include <cuda_runtime.h>
#include <cuda_bf16.h>

// Problem constants
#define BB   64      // batch (inputs)
#define MM   256     // modes
#define KK   4096    // spatial (64*64)

#define KC      64   // K per CTA chunk
#define KSPLIT  64   // KK / KC
#define MT      32   // modes per CTA (one per lane)
#define MTILES  8    // MM / MT
#define KQ      16   // float4 (and ulonglong2) per row
#define EPS_C   0.0009f

// Deterministic partial buffers (no cudaMalloc allowed)
__device__ __align__(16) float g_dot[KSPLIT * BB * MM];   // [s][b][m]  4 MB
__device__ __align__(16) float g_fss[KSPLIT * BB];        // [s][b]
__device__ __align__(16) float g_mss[KSPLIT * MM];        // [s][m]

__device__ __forceinline__ unsigned long long fma2(unsigned long long a,
                                                   unsigned long long b,
                                                   unsigned long long c) {
    unsigned long long d;
    asm("fma.rn.f32x2 %0, %1, %2, %3;" : "=l"(d) : "l"(a), "l"(b), "l"(c));
    return d;
}

__device__ __forceinline__ float2 ull2f2(unsigned long long u) {
    float2 f;
    f.x = __uint_as_float((unsigned int)u);
    f.y = __uint_as_float((unsigned int)(u >> 32));
    return f;
}

// ===== GEMM. CTA (mt, ks): dot[b=0..63][m = mt*32 .. +31] over 64-wide k-chunk.
// 24 KB smem/CTA, 512 CTAs -> ~3.5 CTAs/SM for latency hiding.
__global__ __launch_bounds__(256, 4)
void gemm_partial_kernel(const float* __restrict__ inp,
                         const float* __restrict__ mds,
                         unsigned int* __restrict__ outu) {
    __shared__ float As[BB * KC];   // 16 KB, k-major, unswizzled
    __shared__ float Bs[MT * KC];   //  8 KB, k-major, kq ^ (m&7) swizzle

    const int mt = blockIdx.x;
    const int ks = blockIdx.y;
    const int kbase = ks * KC;
    const int mbase = mt * MT;
    const int tid  = threadIdx.x;
    const int lane = tid & 31;
    const int w    = tid >> 5;

    // init output for finalize's atomicMin (one CTA; stream order protects it)
    if (mt == 0 && ks == 0 && tid < BB) outu[tid] = 0x7f7f7f7fu;

    float4* As4 = reinterpret_cast<float4*>(As);
    float4* Bs4 = reinterpret_cast<float4*>(Bs);

    // ---- stage A: 64 rows x 16 float4, coalesced ----
#pragma unroll
    for (int i = 0; i < 4; ++i) {
        int j  = i * 256 + tid;
        int b  = j >> 4;
        int kq = j & 15;
        As4[b * KQ + kq] =
            *(reinterpret_cast<const float4*>(inp + (size_t)b * KK + kbase) + kq);
    }
    // ---- stage B: 32 rows x 16 float4, swizzled ----
#pragma unroll
    for (int i = 0; i < 2; ++i) {
        int j  = i * 256 + tid;
        int m  = j >> 4;
        int kq = j & 15;
        Bs4[m * KQ + (kq ^ (m & 7))] =
            *(reinterpret_cast<const float4*>(mds + (size_t)(mbase + m) * KK + kbase) + kq);
    }
    __syncthreads();

    // ---- main loop: lane's m fixed, 8 b-rows per warp, f32x2 over k-pairs ----
    const int c = lane & 7;
    const ulonglong2* As2 = reinterpret_cast<const ulonglong2*>(As);
    const ulonglong2* Bs2 = reinterpret_cast<const ulonglong2*>(Bs);

    unsigned long long acc[8];
#pragma unroll
    for (int r = 0; r < 8; ++r) acc[r] = 0ull;

#pragma unroll
    for (int kq = 0; kq < KQ; ++kq) {
        ulonglong2 bv = Bs2[lane * KQ + (kq ^ c)];      // lane-distinct, 4 phases
#pragma unroll
        for (int r = 0; r < 8; ++r) {
            ulonglong2 av = As2[(8 * w + r) * KQ + kq]; // warp-broadcast, 1 phase
            acc[r] = fma2(av.x, bv.x, acc[r]);
            acc[r] = fma2(av.y, bv.y, acc[r]);
        }
    }

    // ---- epilogue: reduce k-parity lanes, coalesced store ----
#pragma unroll
    for (int r = 0; r < 8; ++r) {
        float2 e = ull2f2(acc[r]);
        g_dot[((size_t)ks * BB + 8 * w + r) * MM + mbase + lane] = e.x + e.y;
    }

    // ---- partial squared norms (half-warp per 16-float4 row) ----
    const int hk = lane & 15;
    const int hh = lane >> 4;
    // mode norms: 32 rows, warp w handles rows 4w .. 4w+3
#pragma unroll
    for (int r = 0; r < 2; ++r) {
        int m = 4 * w + 2 * r + hh;
        float4 v = Bs4[m * KQ + (hk ^ (m & 7))];
        float s = v.x * v.x + v.y * v.y + v.z * v.z + v.w * v.w;
#pragma unroll
        for (int o = 8; o > 0; o >>= 1) s += __shfl_xor_sync(0xffffffffu, s, o);
        if (hk == 0) g_mss[ks * MM + mbase + m] = s;
    }
    // input norms: only mt==0 column writes
    if (mt == 0) {
#pragma unroll
        for (int r = 0; r < 4; ++r) {
            int b = 8 * w + 2 * r + hh;
            float4 v = As4[b * KQ + hk];
            float s = v.x * v.x + v.y * v.y + v.z * v.z + v.w * v.w;
#pragma unroll
            for (int o = 8; o > 0; o >>= 1) s += __shfl_xor_sync(0xffffffffu, s, o);
            if (hk == 0) g_fss[ks * BB + b] = s;
        }
    }
}

// ===== Finalize: grid (64 b, 4 mchunks), block 256 = (64 modes x 4 split-qtrs).
// Thread sums 16 split-partials (MLP 16); 4-way smem combine; metric; warp-min;
// atomicMin into out (nonneg floats: uint order == float order).
__global__ __launch_bounds__(256)
void finalize_kernel(unsigned int* __restrict__ outu) {
    __shared__ float sd[4][64];
    __shared__ float sm_[4][64];
    __shared__ float sf[4];

    const int b  = blockIdx.x;
    const int mc = blockIdx.y;          // 0..3
    const int ml = threadIdx.x & 63;    // mode within chunk
    const int sq = threadIdx.x >> 6;    // split-quarter 0..3
    const int m  = mc * 64 + ml;

    float dot = 0.f, mss = 0.f, fss = 0.f;
#pragma unroll
    for (int i = 0; i < 16; ++i) {
        int s = sq * 16 + i;
        dot += g_dot[((size_t)s * BB + b) * MM + m];
        mss += g_mss[s * MM + m];
        fss += g_fss[s * BB + b];       // uniform across ml -> cache-served
    }
    sd[sq][ml]  = dot;
    sm_[sq][ml] = mss;
    if (ml == 0) sf[sq] = fss;
    __syncthreads();

    if (sq == 0) {
        dot = sd[0][ml] + sd[1][ml] + sd[2][ml] + sd[3][ml];
        mss = sm_[0][ml] + sm_[1][ml] + sm_[2][ml] + sm_[3][ml];
        fss = sf[0] + sf[1] + sf[2] + sf[3];

        float fn = sqrtf(fss);
        float mn = sqrtf(mss);
        float cc = dot / (fn * mn);
        float dn = sqrtf(fmaxf(2.f - 2.f * cc, 0.f));
        float lum = (2.f * fn * mn + EPS_C) / (fss + mss + EPS_C);
        float metric = (1.f - (2.f - dn) * 0.5f * sqrtf(lum)) * 2.f;

#pragma unroll
        for (int o = 16; o > 0; o >>= 1)
            metric = fminf(metric, __shfl_xor_sync(0xffffffffu, metric, o));
        if ((threadIdx.x & 31) == 0)
            atomicMin(&outu[b], __float_as_uint(metric));
    }
}

extern "C" void kernel_launch(void* const* d_in, const int* in_sizes, int n_in,
                              void* d_out, int out_size) {
    const float* inp = (const float*)d_in[0];
    const float* mds = (const float*)d_in[1];
    if (in_sizes[0] > in_sizes[1]) {   // identify by element count
        const float* t = inp; inp = mds; mds = t;
    }

    dim3 ggrid(MTILES, KSPLIT);
    gemm_partial_kernel<<<ggrid, 256>>>(inp, mds, (unsigned int*)d_out);

    dim3 fgrid(BB, MM / 64);
    finalize_kernel<<<fgrid, 256>>>((unsigned int*)d_out);
}

// round 7
// speedup vs baseline: 1.5668x; 1.5668x over previous
#include <cuda_runtime.h>
#include <cuda_bf16.h>

// Problem constants
#define BB   64      // batch (inputs)
#define MM   256     // modes
#define KK   4096    // spatial (64*64)

#define KC      128  // K per CTA chunk
#define KSPLIT  32   // KK / KC
#define MT      64   // modes per CTA (2 per lane)
#define MTILES  4    // MM / MT
#define F4R     32   // float4 / ulonglong2 units per row (KC/4)
#define NTHR    256
#define EPS_C   0.0009f

// Deterministic partial buffers (no cudaMalloc allowed)
__device__ __align__(16) float g_dot[KSPLIT * BB * MM];   // [s][b][m]  2 MB
__device__ __align__(16) float g_fss[KSPLIT * BB];        // [s][b]
__device__ __align__(16) float g_mss[KSPLIT * MM];        // [s][m]

__device__ __forceinline__ unsigned long long fma2(unsigned long long a,
                                                   unsigned long long b,
                                                   unsigned long long c) {
    unsigned long long d;
    asm("fma.rn.f32x2 %0, %1, %2, %3;" : "=l"(d) : "l"(a), "l"(b), "l"(c));
    return d;
}

__device__ __forceinline__ float2 ull2f2(unsigned long long u) {
    float2 f;
    f.x = __uint_as_float((unsigned int)u);
    f.y = __uint_as_float((unsigned int)(u >> 32));
    return f;
}

// ===== GEMM. CTA (mt, ks): dot[b=0..63][m = mt*64 .. +63] over k-chunk ks.
// 128 CTAs (~one wave), 64 KB smem, 0.5 crossbar-phase per FFMA2.
__global__ __launch_bounds__(NTHR)
void gemm_partial_kernel(const float* __restrict__ inp,
                         const float* __restrict__ mds) {
    __shared__ float As[BB * KC];    // 32 KB, k-major, unswizzled
    __shared__ float Bs[MT * KC];    // 32 KB, k-major, kq ^ (m&7) swizzle

    const int mt = blockIdx.x;
    const int ks = blockIdx.y;
    const int kbase = ks * KC;
    const int mbase = mt * MT;
    const int tid  = threadIdx.x;
    const int lane = tid & 31;
    const int w    = tid >> 5;       // 0..7

    float4* As4 = reinterpret_cast<float4*>(As);
    float4* Bs4 = reinterpret_cast<float4*>(Bs);

    // ---- stage A: 64 rows x 32 float4, coalesced ----
#pragma unroll
    for (int i = 0; i < 8; ++i) {
        int j  = i * NTHR + tid;
        int b  = j >> 5;
        int kq = j & 31;
        As4[b * F4R + kq] =
            *(reinterpret_cast<const float4*>(inp + (size_t)b * KK + kbase) + kq);
    }
    // ---- stage B: 64 rows x 32 float4, swizzled ----
#pragma unroll
    for (int i = 0; i < 8; ++i) {
        int j  = i * NTHR + tid;
        int m  = j >> 5;
        int kq = j & 31;
        Bs4[m * F4R + (kq ^ (m & 7))] =
            *(reinterpret_cast<const float4*>(mds + (size_t)(mbase + m) * KK + kbase) + kq);
    }
    __syncthreads();

    // ---- main loop: lane owns m = lane and lane+32; warp owns 8 b-rows ----
    const int c = lane & 7;          // swizzle const (same for lane, lane+32)
    const ulonglong2* As2 = reinterpret_cast<const ulonglong2*>(As);
    const ulonglong2* Bs2 = reinterpret_cast<const ulonglong2*>(Bs);

    unsigned long long acc[8][2];
#pragma unroll
    for (int r = 0; r < 8; ++r) { acc[r][0] = 0ull; acc[r][1] = 0ull; }

#pragma unroll 4
    for (int kq = 0; kq < F4R; ++kq) {
        ulonglong2 bv0 = Bs2[lane * F4R + (kq ^ c)];          // 4 phases
        ulonglong2 bv1 = Bs2[(lane + 32) * F4R + (kq ^ c)];   // 4 phases
#pragma unroll
        for (int r = 0; r < 8; ++r) {
            ulonglong2 av = As2[(8 * w + r) * F4R + kq];      // broadcast, 1 phase
            acc[r][0] = fma2(av.x, bv0.x, acc[r][0]);
            acc[r][0] = fma2(av.y, bv0.y, acc[r][0]);
            acc[r][1] = fma2(av.x, bv1.x, acc[r][1]);
            acc[r][1] = fma2(av.y, bv1.y, acc[r][1]);
        }
    }

    // ---- epilogue: reduce k-parity, coalesced partial-dot stores ----
#pragma unroll
    for (int r = 0; r < 8; ++r) {
        int b = 8 * w + r;
        float2 e0 = ull2f2(acc[r][0]);
        float2 e1 = ull2f2(acc[r][1]);
        g_dot[((size_t)ks * BB + b) * MM + mbase + lane]      = e0.x + e0.y;
        g_dot[((size_t)ks * BB + b) * MM + mbase + 32 + lane] = e1.x + e1.y;
    }

    // ---- partial squared norms (one warp per row, 32 float4/row) ----
    // mode norms: warp w handles rows 8w..8w+7 of this CTA's 64-mode slice
#pragma unroll
    for (int r = 0; r < 8; ++r) {
        int m = 8 * w + r;
        float4 v = Bs4[m * F4R + (lane ^ (m & 7))];
        float s = v.x * v.x + v.y * v.y + v.z * v.z + v.w * v.w;
#pragma unroll
        for (int o = 16; o > 0; o >>= 1) s += __shfl_xor_sync(0xffffffffu, s, o);
        if (lane == 0) g_mss[ks * MM + mbase + m] = s;
    }
    // input norms: only mt==0 column writes (one writer per [ks][b])
    if (mt == 0) {
#pragma unroll
        for (int r = 0; r < 8; ++r) {
            int b = 8 * w + r;
            float4 v = As4[b * F4R + lane];
            float s = v.x * v.x + v.y * v.y + v.z * v.z + v.w * v.w;
#pragma unroll
            for (int o = 16; o > 0; o >>= 1) s += __shfl_xor_sync(0xffffffffu, s, o);
            if (lane == 0) g_fss[ks * BB + b] = s;
        }
    }
}

// ===== Finalize: grid 64 (one CTA per b), 256 threads (one per mode).
// No atomics, no init: block-min then a single direct store.
__global__ __launch_bounds__(NTHR)
void finalize_kernel(float* __restrict__ out) {
    __shared__ float red[8];

    const int b = blockIdx.x;
    const int m = threadIdx.x;

    float dot = 0.f, mss = 0.f;
#pragma unroll 8
    for (int s = 0; s < KSPLIT; ++s) {
        dot += g_dot[((size_t)s * BB + b) * MM + m];   // coalesced across m
        mss += g_mss[s * MM + m];
    }
    float fss = 0.f;
#pragma unroll 8
    for (int s = 0; s < KSPLIT; ++s)
        fss += g_fss[s * BB + b];                      // uniform -> broadcast

    float fn = sqrtf(fss);
    float mn = sqrtf(mss);
    float cc = dot / (fn * mn);
    float dn = sqrtf(fmaxf(2.f - 2.f * cc, 0.f));
    float lum = (2.f * fn * mn + EPS_C) / (fss + mss + EPS_C);
    float metric = (1.f - (2.f - dn) * 0.5f * sqrtf(lum)) * 2.f;

#pragma unroll
    for (int o = 16; o > 0; o >>= 1)
        metric = fminf(metric, __shfl_xor_sync(0xffffffffu, metric, o));
    if ((m & 31) == 0) red[m >> 5] = metric;
    __syncthreads();
    if (m == 0) {
        float v = red[0];
#pragma unroll
        for (int i = 1; i < 8; ++i) v = fminf(v, red[i]);
        out[b] = v;
    }
}

extern "C" void kernel_launch(void* const* d_in, const int* in_sizes, int n_in,
                              void* d_out, int out_size) {
    const float* inp = (const float*)d_in[0];
    const float* mds = (const float*)d_in[1];
    if (in_sizes[0] > in_sizes[1]) {   // identify by element count
        const float* t = inp; inp = mds; mds = t;
    }

    dim3 ggrid(MTILES, KSPLIT);        // 4 x 32 = 128 CTAs (~1 wave)
    gemm_partial_kernel<<<ggrid, NTHR>>>(inp, mds);

    finalize_kernel<<<BB, NTHR>>>((float*)d_out);
}